// round 11
// baseline (speedup 1.0000x reference)
#include <cuda_runtime.h>
#include <cuda_fp16.h>
#include <cstdint>
#include <math.h>

// Problem dims
#define Bb 8
#define Nn 1024
#define Ss 1024
#define Cc 768
#define Hh_ 12
#define Dd 64
#define SCALEF 0.125f

// ---------------------------------------------------------------------------
// Scratch (static __device__ — allocation-free per harness rules)
// ---------------------------------------------------------------------------
__device__ __half g_q16[(long long)Bb * Nn * Cc];
__device__ __half g_k16[(long long)Bb * Ss * Cc];
__device__ __half g_v16[(long long)Bb * Ss * Cc];
__device__ __half g_Wq16[Cc * Cc];
__device__ __half g_Wk16[Cc * Cc];
__device__ __half g_Wv16[Cc * Cc];
__device__ __half g_Wo16[Cc * Cc];
__device__ __half g_Q16[(long long)Bb * Nn * Cc];   // pre-scaled by 0.125
__device__ __half g_K16[(long long)Bb * Ss * Cc];
__device__ __half g_V16[(long long)Bb * Ss * Cc];
__device__ __half g_O16[(long long)Bb * Nn * Cc];   // head outputs

// ---------------------------------------------------------------------------
// PTX helpers
// ---------------------------------------------------------------------------
__device__ __forceinline__ unsigned s2u32(const void* p) {
    return (unsigned)__cvta_generic_to_shared(p);
}
__device__ __forceinline__ void ldsm4(unsigned* r, unsigned addr) {
    asm volatile("ldmatrix.sync.aligned.m8n8.x4.shared.b16 {%0,%1,%2,%3}, [%4];"
                 : "=r"(r[0]), "=r"(r[1]), "=r"(r[2]), "=r"(r[3]) : "r"(addr));
}
__device__ __forceinline__ void ldsm2(unsigned* r, unsigned addr) {
    asm volatile("ldmatrix.sync.aligned.m8n8.x2.shared.b16 {%0,%1}, [%2];"
                 : "=r"(r[0]), "=r"(r[1]) : "r"(addr));
}
__device__ __forceinline__ void ldsm2t(unsigned* r, unsigned addr) {
    asm volatile("ldmatrix.sync.aligned.m8n8.x2.trans.shared.b16 {%0,%1}, [%2];"
                 : "=r"(r[0]), "=r"(r[1]) : "r"(addr));
}
__device__ __forceinline__ void mma16816(float* d, const unsigned* a, const unsigned* b) {
    asm volatile("mma.sync.aligned.m16n8k16.row.col.f32.f16.f16.f32 "
                 "{%0,%1,%2,%3}, {%4,%5,%6,%7}, {%8,%9}, {%0,%1,%2,%3};"
                 : "+f"(d[0]), "+f"(d[1]), "+f"(d[2]), "+f"(d[3])
                 : "r"(a[0]), "r"(a[1]), "r"(a[2]), "r"(a[3]), "r"(b[0]), "r"(b[1]));
}
__device__ __forceinline__ void cpa16(unsigned dst, const void* src) {
    asm volatile("cp.async.cg.shared.global [%0], [%1], 16;" :: "r"(dst), "l"(src));
}
__device__ __forceinline__ void cpcommit() {
    asm volatile("cp.async.commit_group;");
}
template<int N>
__device__ __forceinline__ void cpwait() {
    asm volatile("cp.async.wait_group %0;" :: "n"(N));
}
__device__ __forceinline__ unsigned packh2(float a, float b) {
    __half2 h = __floats2half2_rn(a, b);
    return *reinterpret_cast<unsigned*>(&h);
}
__device__ __forceinline__ float quadSum(float v) {
    v += __shfl_xor_sync(0xffffffffu, v, 1);
    v += __shfl_xor_sync(0xffffffffu, v, 2);
    return v;
}

// Epilogue pair-store overloads
__device__ __forceinline__ void store2(__half* C, long long off, float v0, float v1) {
    __half2* p = (__half2*)(C + off);
    *p = __floats2half2_rn(v0, v1);
}
__device__ __forceinline__ void store2(float* C, long long off, float v0, float v1) {
    float2* p = (float2*)(C + off);
    *p = make_float2(v0, v1);
}

// ---------------------------------------------------------------------------
// Core NT GEMM with 3-stage cp.async pipeline (unchanged from R10 winner).
// ---------------------------------------------------------------------------
#define GEMM_LDSW 40
#define GEMM_TILE (128 * GEMM_LDSW)
#define GEMM_SMEM_BYTES (3 * 2 * GEMM_TILE * 2)  // 61440

template<typename OutT, bool BIAS>
__device__ __forceinline__
void hgemm_nt_body(const __half* __restrict__ A, const __half* __restrict__ B,
                   OutT* __restrict__ C, int Kdim, int lda, int ldb, int ldc,
                   float scale, const float* __restrict__ bias,
                   int m0, int n0, __half* dsm)
{
    const int LDSW = GEMM_LDSW;

    int tid = threadIdx.x;
    int lane = tid & 31;
    int w = tid >> 5;
    int wm = w & 3;
    int wn = w >> 2;

    int grow = tid >> 2;
    int gchk = tid & 3;
    const __half* gA0 = A + (long long)(m0 + grow) * lda + gchk * 8;
    const __half* gA1 = gA0 + 64ll * lda;
    const __half* gB0 = B + (long long)(n0 + grow) * ldb + gchk * 8;
    const __half* gB1 = gB0 + 64ll * ldb;

    unsigned ssAb = (unsigned)((grow * LDSW + gchk * 8) * 2);

    unsigned base = s2u32(dsm);
    unsigned asu[3], bsu[3];
    #pragma unroll
    for (int s = 0; s < 3; s++) {
        asu[s] = base + (unsigned)(s * 2 * GEMM_TILE * 2);
        bsu[s] = asu[s] + (unsigned)(GEMM_TILE * 2);
    }

    int aBase = (wm * 32 + (lane & 15)) * LDSW + (lane >> 4) * 8;
    int bBase = (wn * 64 + (lane & 7)) * LDSW + ((lane >> 3) & 1) * 8;

    float acc[2][8][4];
    #pragma unroll
    for (int i = 0; i < 2; i++)
        #pragma unroll
        for (int j = 0; j < 8; j++) {
            acc[i][j][0] = 0.f; acc[i][j][1] = 0.f;
            acc[i][j][2] = 0.f; acc[i][j][3] = 0.f;
        }

    int nk = Kdim >> 5;

    #pragma unroll
    for (int pt = 0; pt < 2; pt++) {
        if (pt < nk) {
            int k0 = pt << 5;
            cpa16(asu[pt] + ssAb, gA0 + k0);
            cpa16(asu[pt] + ssAb + 64u * LDSW * 2u, gA1 + k0);
            cpa16(bsu[pt] + ssAb, gB0 + k0);
            cpa16(bsu[pt] + ssAb + 64u * LDSW * 2u, gB1 + k0);
        }
        cpcommit();
    }

    int stage = 0;
    for (int kt = 0; kt < nk; kt++) {
        cpwait<1>();
        __syncthreads();

        if (kt + 2 < nk) {
            int s2i = (stage + 2 >= 3) ? stage - 1 : stage + 2;
            int k0 = (kt + 2) << 5;
            cpa16(asu[s2i] + ssAb, gA0 + k0);
            cpa16(asu[s2i] + ssAb + 64u * LDSW * 2u, gA1 + k0);
            cpa16(bsu[s2i] + ssAb, gB0 + k0);
            cpa16(bsu[s2i] + ssAb + 64u * LDSW * 2u, gB1 + k0);
        }
        cpcommit();

        unsigned as_ = asu[stage];
        unsigned bs_ = bsu[stage];
        #pragma unroll
        for (int kk = 0; kk < 2; kk++) {
            unsigned af[2][4];
            unsigned bf[8][2];
            #pragma unroll
            for (int mt = 0; mt < 2; mt++)
                ldsm4(af[mt], as_ + 2u * (unsigned)(aBase + mt * 16 * LDSW + kk * 16));
            #pragma unroll
            for (int nt = 0; nt < 8; nt++)
                ldsm2(bf[nt], bs_ + 2u * (unsigned)(bBase + nt * 8 * LDSW + kk * 16));
            #pragma unroll
            for (int mt = 0; mt < 2; mt++)
                #pragma unroll
                for (int nt = 0; nt < 8; nt++)
                    mma16816(acc[mt][nt], af[mt], bf[nt]);
        }
        stage = (stage + 1 == 3) ? 0 : stage + 1;
    }

    #pragma unroll
    for (int mt = 0; mt < 2; mt++) {
        int r0 = m0 + wm * 32 + mt * 16 + (lane >> 2);
        #pragma unroll
        for (int nt = 0; nt < 8; nt++) {
            int c0 = n0 + wn * 64 + nt * 8 + (lane & 3) * 2;
            float v0 = acc[mt][nt][0] * scale;
            float v1 = acc[mt][nt][1] * scale;
            float v2 = acc[mt][nt][2] * scale;
            float v3 = acc[mt][nt][3] * scale;
            if (BIAS) {
                float bc0 = bias[c0];
                float bc1 = bias[c0 + 1];
                v0 += bc0; v1 += bc1; v2 += bc0; v3 += bc1;
            }
            store2(C, (long long)r0 * ldc + c0, v0, v1);
            store2(C, (long long)(r0 + 8) * ldc + c0, v2, v3);
        }
    }
}

__global__ __launch_bounds__(256)
void hgemm_proj3(const __half* __restrict__ x0, const __half* __restrict__ x1,
                 const __half* __restrict__ x2,
                 const __half* __restrict__ W0, const __half* __restrict__ W1,
                 const __half* __restrict__ W2,
                 __half* __restrict__ C0, __half* __restrict__ C1,
                 __half* __restrict__ C2)
{
    extern __shared__ __half dsm[];

    int z = blockIdx.z;
    const __half* A = (z == 0) ? x0 : (z == 1) ? x1 : x2;
    const __half* B = (z == 0) ? W0 : (z == 1) ? W1 : W2;
    __half* C = (z == 0) ? C0 : (z == 1) ? C1 : C2;
    float scale = (z == 0) ? SCALEF : 1.0f;

    hgemm_nt_body<__half, false>(A, B, C, Cc, Cc, Cc, Cc, scale, nullptr,
                                 blockIdx.y * 128, blockIdx.x * 128, dsm);
}

__global__ __launch_bounds__(256)
void hgemm_out(const __half* __restrict__ A, const __half* __restrict__ B,
               float* __restrict__ C, const float* __restrict__ bias)
{
    extern __shared__ __half dsm[];

    hgemm_nt_body<float, true>(A, B, C, Cc, Cc, Cc, Cc, 1.0f, bias,
                               blockIdx.y * 128, blockIdx.x * 128, dsm);
}

// ---------------------------------------------------------------------------
// Fused attention, shift-free softmax, cp.async double-buffered K/V.
// Dynamic smem: Ks[2] + Vs[2], each 128 x 72 halves = 73728 B total
// (2 CTAs x 72KB = 144KB <= 228KB, occupancy-2 compatible).
// Prefetch for chunk c+1 is issued AFTER the iteration barrier (all warps
// done computing chunk c-1's buffer) — fixes R5's latent ordering race.
// ---------------------------------------------------------------------------
#define ATT_LW 72
#define ATT_TILE (128 * ATT_LW)                    // halves
#define ATT_SMEM_BYTES (4 * ATT_TILE * 2)          // 73728

__global__ __launch_bounds__(256)
void fused_attn(const __half* __restrict__ Q, const __half* __restrict__ K,
                const __half* __restrict__ V,
                const float* __restrict__ aw, float* __restrict__ log_attn,
                __half* __restrict__ O)
{
    const int LW = ATT_LW;

    extern __shared__ __half sm[];
    unsigned ksu[2], vsu[2];
    ksu[0] = s2u32(sm);
    ksu[1] = ksu[0] + (unsigned)(ATT_TILE * 2);
    vsu[0] = ksu[1] + (unsigned)(ATT_TILE * 2);
    vsu[1] = vsu[0] + (unsigned)(ATT_TILE * 2);

    int qblk = blockIdx.x;             // 0..7
    int bh = blockIdx.y;               // 0..95
    int b = bh / Hh_;
    int h = bh - b * Hh_;

    const __half* Qp = Q + ((long long)b * Nn + qblk * 128) * Cc + h * Dd;
    const __half* Kp = K + (long long)b * Ss * Cc + h * Dd;
    const __half* Vp = V + (long long)b * Ss * Cc + h * Dd;
    const float* awp = aw + ((long long)bh * Nn + qblk * 128) * Ss;
    float* lap = log_attn + ((long long)bh * Nn + qblk * 128) * Ss;

    int tid = threadIdx.x;
    int lane = tid & 31;
    int wm = tid >> 5;

    int ldr = tid >> 3;                // 0..31 (row group)
    int ldc_ = (tid & 7) * 8;          // 16B chunk within row
    unsigned ssb = (unsigned)((ldr * LW + ldc_) * 2);   // byte offset in tile

    // ---- load Q tile into Ks buf0, extract A fragments ----
    #pragma unroll
    for (int i = 0; i < 4; i++) {
        int row = ldr + i * 32;
        *(uint4*)&sm[row * LW + ldc_] = *(const uint4*)(Qp + (long long)row * Cc + ldc_);
    }
    __syncthreads();

    unsigned qf[4][4];
    {
        int aBase = (wm * 16 + (lane & 15)) * LW + (lane >> 4) * 8;
        #pragma unroll
        for (int k = 0; k < 4; k++)
            ldsm4(qf[k], ksu[0] + 2u * (unsigned)(aBase + k * 16));
    }
    __syncthreads();

    int bBaseK = (lane & 7) * LW + ((lane >> 3) & 1) * 8;

    // ================= PASS 1: LSE (shift-free), K double-buffered ==========
    float s1[2] = { 0.f, 0.f };

    // prologue: issue K0 -> buf0
    #pragma unroll
    for (int i = 0; i < 4; i++)
        cpa16(ksu[0] + ssb + (unsigned)(i * 32 * LW * 2),
              Kp + (long long)(ldr + i * 32) * Cc + ldc_);
    cpcommit();

    for (int c = 0; c < 8; c++) {
        int cur = c & 1;
        cpwait<0>();            // K(c) resident
        __syncthreads();        // all warps past compute(c-1) before refill
        if (c + 1 < 8) {
            int nb = cur ^ 1;
            #pragma unroll
            for (int i = 0; i < 4; i++)
                cpa16(ksu[nb] + ssb + (unsigned)(i * 32 * LW * 2),
                      Kp + (long long)((c + 1) * 128 + ldr + i * 32) * Cc + ldc_);
        }
        cpcommit();

        float sacc[16][4];
        #pragma unroll
        for (int nt = 0; nt < 16; nt++) {
            sacc[nt][0] = 0.f; sacc[nt][1] = 0.f;
            sacc[nt][2] = 0.f; sacc[nt][3] = 0.f;
        }
        #pragma unroll
        for (int kk = 0; kk < 4; kk++) {
            #pragma unroll
            for (int nt = 0; nt < 16; nt++) {
                unsigned bf[2];
                ldsm2(bf, ksu[cur] + 2u * (unsigned)(bBaseK + nt * 8 * LW + kk * 16));
                mma16816(sacc[nt], qf[kk], bf);
            }
        }

        #pragma unroll
        for (int nt = 0; nt < 16; nt++) {
            s1[0] += __expf(sacc[nt][0]) + __expf(sacc[nt][1]);
            s1[1] += __expf(sacc[nt][2]) + __expf(sacc[nt][3]);
        }
    }

    float lse[2];
    lse[0] = __logf(quadSum(s1[0]));
    lse[1] = __logf(quadSum(s1[1]));

    // ================= PASS 2: logits + PV, K/V double-buffered =============
    float s2[2] = { 0.f, 0.f };
    float oacc[8][4];
    #pragma unroll
    for (int nd = 0; nd < 8; nd++) {
        oacc[nd][0] = 0.f; oacc[nd][1] = 0.f;
        oacc[nd][2] = 0.f; oacc[nd][3] = 0.f;
    }

    int rowL0 = wm * 16 + (lane >> 2);
    int colQ = (lane & 3) * 2;

    // barrier: pass-1 compute on buf0/buf1 finished before refill (c=7 used buf1;
    // issuing into buf0 races pass-1 c=7 compute of other warps without this)
    __syncthreads();

    // prologue: issue K0+V0 -> buf0
    #pragma unroll
    for (int i = 0; i < 4; i++) {
        cpa16(ksu[0] + ssb + (unsigned)(i * 32 * LW * 2),
              Kp + (long long)(ldr + i * 32) * Cc + ldc_);
        cpa16(vsu[0] + ssb + (unsigned)(i * 32 * LW * 2),
              Vp + (long long)(ldr + i * 32) * Cc + ldc_);
    }
    cpcommit();

    for (int c = 0; c < 8; c++) {
        int cur = c & 1;
        cpwait<0>();
        __syncthreads();
        if (c + 1 < 8) {
            int nb = cur ^ 1;
            #pragma unroll
            for (int i = 0; i < 4; i++) {
                cpa16(ksu[nb] + ssb + (unsigned)(i * 32 * LW * 2),
                      Kp + (long long)((c + 1) * 128 + ldr + i * 32) * Cc + ldc_);
                cpa16(vsu[nb] + ssb + (unsigned)(i * 32 * LW * 2),
                      Vp + (long long)((c + 1) * 128 + ldr + i * 32) * Cc + ldc_);
            }
        }
        cpcommit();

        float sacc[16][4];
        #pragma unroll
        for (int nt = 0; nt < 16; nt++) {
            sacc[nt][0] = 0.f; sacc[nt][1] = 0.f;
            sacc[nt][2] = 0.f; sacc[nt][3] = 0.f;
        }
        #pragma unroll
        for (int kk = 0; kk < 4; kk++) {
            #pragma unroll
            for (int nt = 0; nt < 16; nt++) {
                unsigned bf[2];
                ldsm2(bf, ksu[cur] + 2u * (unsigned)(bBaseK + nt * 8 * LW + kk * 16));
                mma16816(sacc[nt], qf[kk], bf);
            }
        }

        // single sweep: logits -> log_attn, p = exp(g) -> sacc, sums
        #pragma unroll
        for (int nt = 0; nt < 16; nt++) {
            long long off0 = (long long)rowL0 * Ss + c * 128 + nt * 8 + colQ;
            long long off1 = off0 + 8ll * Ss;
            float2 wa = *(const float2*)(awp + off0);
            float2 wb = *(const float2*)(awp + off1);
            float g0 = wa.x + sacc[nt][0] - lse[0];
            float g1 = wa.y + sacc[nt][1] - lse[0];
            float g2 = wb.x + sacc[nt][2] - lse[1];
            float g3 = wb.y + sacc[nt][3] - lse[1];
            *(float2*)(lap + off0) = make_float2(g0, g1);
            *(float2*)(lap + off1) = make_float2(g2, g3);
            float p0 = __expf(g0);
            float p1 = __expf(g1);
            float p2 = __expf(g2);
            float p3 = __expf(g3);
            sacc[nt][0] = p0; sacc[nt][1] = p1;
            sacc[nt][2] = p2; sacc[nt][3] = p3;
            s2[0] += p0 + p1;
            s2[1] += p2 + p3;
        }

        // PV: probs (m16 x k128) @ V (k128 x n64), V fragments via ldsm.trans
        #pragma unroll
        for (int kk = 0; kk < 8; kk++) {
            unsigned pa[4];
            pa[0] = packh2(sacc[2 * kk][0], sacc[2 * kk][1]);
            pa[1] = packh2(sacc[2 * kk][2], sacc[2 * kk][3]);
            pa[2] = packh2(sacc[2 * kk + 1][0], sacc[2 * kk + 1][1]);
            pa[3] = packh2(sacc[2 * kk + 1][2], sacc[2 * kk + 1][3]);
            unsigned vrow = vsu[cur] + 2u * (unsigned)((kk * 16 + (lane & 15)) * LW);
            #pragma unroll
            for (int nd = 0; nd < 8; nd++) {
                unsigned bf[2];
                ldsm2t(bf, vrow + 2u * (unsigned)(nd * 8));
                mma16816(oacc[nd], pa, bf);
            }
        }
    }

    // epilogue: normalize by sum(p)
    float inv0 = 1.0f / quadSum(s2[0]);
    float inv1 = 1.0f / quadSum(s2[1]);
    int gr0 = qblk * 128 + rowL0;
    #pragma unroll
    for (int nd = 0; nd < 8; nd++) {
        int col = h * Dd + nd * 8 + colQ;
        __half* p0 = O + ((long long)b * Nn + gr0) * Cc + col;
        __half* p1 = O + ((long long)b * Nn + gr0 + 8) * Cc + col;
        *(__half2*)p0 = __floats2half2_rn(oacc[nd][0] * inv0, oacc[nd][1] * inv0);
        *(__half2*)p1 = __floats2half2_rn(oacc[nd][2] * inv1, oacc[nd][3] * inv1);
    }
}

// ---------------------------------------------------------------------------
// Batched fp32 -> fp16 conversions
// ---------------------------------------------------------------------------
__global__ __launch_bounds__(256)
void f2h3(const float* __restrict__ p0, const float* __restrict__ p1,
          const float* __restrict__ p2,
          __half* __restrict__ o0, __half* __restrict__ o1,
          __half* __restrict__ o2, int n4)
{
    int i = blockIdx.x * 256 + threadIdx.x;
    if (i >= n4) return;
    int s = blockIdx.y;
    const float* in = (s == 0) ? p0 : (s == 1) ? p1 : p2;
    __half* out = (s == 0) ? o0 : (s == 1) ? o1 : o2;
    float4 v = ((const float4*)in)[i];
    __half2* o = (__half2*)out + 2 * i;
    o[0] = __floats2half2_rn(v.x, v.y);
    o[1] = __floats2half2_rn(v.z, v.w);
}

__global__ __launch_bounds__(256)
void f2h4(const float* __restrict__ p0, const float* __restrict__ p1,
          const float* __restrict__ p2, const float* __restrict__ p3,
          __half* __restrict__ o0, __half* __restrict__ o1,
          __half* __restrict__ o2, __half* __restrict__ o3, int n4)
{
    int i = blockIdx.x * 256 + threadIdx.x;
    if (i >= n4) return;
    int s = blockIdx.y;
    const float* in = (s == 0) ? p0 : (s == 1) ? p1 : (s == 2) ? p2 : p3;
    __half* out = (s == 0) ? o0 : (s == 1) ? o1 : (s == 2) ? o2 : o3;
    float4 v = ((const float4*)in)[i];
    __half2* o = (__half2*)out + 2 * i;
    o[0] = __floats2half2_rn(v.x, v.y);
    o[1] = __floats2half2_rn(v.z, v.w);
}

// ---------------------------------------------------------------------------
extern "C" void kernel_launch(void* const* d_in, const int* in_sizes, int n_in,
                              void* d_out, int out_size)
{
    const float* query = (const float*)d_in[0];
    const float* key   = (const float*)d_in[1];
    const float* value = (const float*)d_in[2];
    const float* aw    = (const float*)d_in[3];
    const float* Wq    = (const float*)d_in[4];
    const float* Wk    = (const float*)d_in[5];
    const float* Wv    = (const float*)d_in[6];
    const float* Wo    = (const float*)d_in[7];
    const float* bo    = (const float*)d_in[8];

    float* out = (float*)d_out;                               // [B,N,C]
    float* log_attn = out + (long long)Bb * Nn * Cc;          // [B,H,N,S]

    __half *q16, *k16, *v16, *Wq16, *Wk16, *Wv16, *Wo16;
    __half *Q16, *K16, *V16, *O16;
    cudaGetSymbolAddress((void**)&q16,  g_q16);
    cudaGetSymbolAddress((void**)&k16,  g_k16);
    cudaGetSymbolAddress((void**)&v16,  g_v16);
    cudaGetSymbolAddress((void**)&Wq16, g_Wq16);
    cudaGetSymbolAddress((void**)&Wk16, g_Wk16);
    cudaGetSymbolAddress((void**)&Wv16, g_Wv16);
    cudaGetSymbolAddress((void**)&Wo16, g_Wo16);
    cudaGetSymbolAddress((void**)&Q16,  g_Q16);
    cudaGetSymbolAddress((void**)&K16,  g_K16);
    cudaGetSymbolAddress((void**)&V16,  g_V16);
    cudaGetSymbolAddress((void**)&O16,  g_O16);

    // opt-in dynamic smem (idempotent)
    cudaFuncSetAttribute(hgemm_proj3,
                         cudaFuncAttributeMaxDynamicSharedMemorySize,
                         GEMM_SMEM_BYTES);
    cudaFuncSetAttribute(hgemm_out,
                         cudaFuncAttributeMaxDynamicSharedMemorySize,
                         GEMM_SMEM_BYTES);
    cudaFuncSetAttribute(fused_attn,
                         cudaFuncAttributeMaxDynamicSharedMemorySize,
                         ATT_SMEM_BYTES);

    const int nInp4 = (Bb * Nn * Cc) / 4;      // 1572864
    const int nW4   = (Cc * Cc) / 4;           // 147456

    // Launch 1-2: conversions (merged so fused_attn is launch #4)
    f2h3<<<dim3((nInp4 + 255) / 256, 3), 256>>>(query, key, value,
                                                q16, k16, v16, nInp4);
    f2h4<<<dim3((nW4 + 255) / 256, 4), 256>>>(Wq, Wk, Wv, Wo,
                                              Wq16, Wk16, Wv16, Wo16, nW4);

    dim3 blk(256);

    // Launch 3: merged Q/K/V projections (Q pre-scaled by SCALE)
    dim3 gProj3(Cc / 128, (Bb * Nn) / 128, 3);
    hgemm_proj3<<<gProj3, blk, GEMM_SMEM_BYTES>>>(q16, k16, v16,
                                                  Wq16, Wk16, Wv16,
                                                  Q16, K16, V16);

    // Launch 4: fused attention (profiled slot)
    fused_attn<<<dim3(Nn / 128, Bb * Hh_), blk, ATT_SMEM_BYTES>>>(
        Q16, K16, V16, aw, log_attn, O16);

    // Launch 5: out = O16 @ Wo16^T + bo
    dim3 gOut(Cc / 128, (Bb * Nn) / 128, 1);
    hgemm_out<<<gOut, blk, GEMM_SMEM_BYTES>>>(O16, Wo16, out, bo);
}

// round 12
// speedup vs baseline: 1.0501x; 1.0501x over previous
#include <cuda_runtime.h>
#include <cuda_fp16.h>
#include <cstdint>
#include <math.h>

// Problem dims
#define Bb 8
#define Nn 1024
#define Ss 1024
#define Cc 768
#define Hh_ 12
#define Dd 64
#define SCALEF 0.125f

// ---------------------------------------------------------------------------
// Scratch (static __device__ — allocation-free per harness rules)
// ---------------------------------------------------------------------------
__device__ __half g_q16[(long long)Bb * Nn * Cc];
__device__ __half g_k16[(long long)Bb * Ss * Cc];
__device__ __half g_v16[(long long)Bb * Ss * Cc];
__device__ __half g_Wq16[Cc * Cc];
__device__ __half g_Wk16[Cc * Cc];
__device__ __half g_Wv16[Cc * Cc];
__device__ __half g_Wo16[Cc * Cc];
__device__ __half g_Q16[(long long)Bb * Nn * Cc];   // pre-scaled by 0.125
__device__ __half g_K16[(long long)Bb * Ss * Cc];
__device__ __half g_V16[(long long)Bb * Ss * Cc];
__device__ __half g_O16[(long long)Bb * Nn * Cc];   // head outputs

// ---------------------------------------------------------------------------
// PTX helpers
// ---------------------------------------------------------------------------
__device__ __forceinline__ unsigned s2u32(const void* p) {
    return (unsigned)__cvta_generic_to_shared(p);
}
__device__ __forceinline__ void ldsm4(unsigned* r, unsigned addr) {
    asm volatile("ldmatrix.sync.aligned.m8n8.x4.shared.b16 {%0,%1,%2,%3}, [%4];"
                 : "=r"(r[0]), "=r"(r[1]), "=r"(r[2]), "=r"(r[3]) : "r"(addr));
}
__device__ __forceinline__ void ldsm2(unsigned* r, unsigned addr) {
    asm volatile("ldmatrix.sync.aligned.m8n8.x2.shared.b16 {%0,%1}, [%2];"
                 : "=r"(r[0]), "=r"(r[1]) : "r"(addr));
}
__device__ __forceinline__ void ldsm2t(unsigned* r, unsigned addr) {
    asm volatile("ldmatrix.sync.aligned.m8n8.x2.trans.shared.b16 {%0,%1}, [%2];"
                 : "=r"(r[0]), "=r"(r[1]) : "r"(addr));
}
__device__ __forceinline__ void mma16816(float* d, const unsigned* a, const unsigned* b) {
    asm volatile("mma.sync.aligned.m16n8k16.row.col.f32.f16.f16.f32 "
                 "{%0,%1,%2,%3}, {%4,%5,%6,%7}, {%8,%9}, {%0,%1,%2,%3};"
                 : "+f"(d[0]), "+f"(d[1]), "+f"(d[2]), "+f"(d[3])
                 : "r"(a[0]), "r"(a[1]), "r"(a[2]), "r"(a[3]), "r"(b[0]), "r"(b[1]));
}
__device__ __forceinline__ void cpa16(unsigned dst, const void* src) {
    asm volatile("cp.async.cg.shared.global [%0], [%1], 16;" :: "r"(dst), "l"(src));
}
__device__ __forceinline__ void cpcommit() {
    asm volatile("cp.async.commit_group;");
}
template<int N>
__device__ __forceinline__ void cpwait() {
    asm volatile("cp.async.wait_group %0;" :: "n"(N));
}
__device__ __forceinline__ unsigned packh2(float a, float b) {
    __half2 h = __floats2half2_rn(a, b);
    return *reinterpret_cast<unsigned*>(&h);
}
__device__ __forceinline__ float quadSum(float v) {
    v += __shfl_xor_sync(0xffffffffu, v, 1);
    v += __shfl_xor_sync(0xffffffffu, v, 2);
    return v;
}

// Epilogue pair-store overloads
__device__ __forceinline__ void store2(__half* C, long long off, float v0, float v1) {
    __half2* p = (__half2*)(C + off);
    *p = __floats2half2_rn(v0, v1);
}
__device__ __forceinline__ void store2(float* C, long long off, float v0, float v1) {
    float2* p = (float2*)(C + off);
    *p = make_float2(v0, v1);
}

// ---------------------------------------------------------------------------
// Core NT GEMM with 3-stage cp.async pipeline (unchanged from R10 winner).
// ---------------------------------------------------------------------------
#define GEMM_LDSW 40
#define GEMM_TILE (128 * GEMM_LDSW)
#define GEMM_SMEM_BYTES (3 * 2 * GEMM_TILE * 2)  // 61440

template<typename OutT, bool BIAS>
__device__ __forceinline__
void hgemm_nt_body(const __half* __restrict__ A, const __half* __restrict__ B,
                   OutT* __restrict__ C, int Kdim, int lda, int ldb, int ldc,
                   float scale, const float* __restrict__ bias,
                   int m0, int n0, __half* dsm)
{
    const int LDSW = GEMM_LDSW;

    int tid = threadIdx.x;
    int lane = tid & 31;
    int w = tid >> 5;
    int wm = w & 3;
    int wn = w >> 2;

    int grow = tid >> 2;
    int gchk = tid & 3;
    const __half* gA0 = A + (long long)(m0 + grow) * lda + gchk * 8;
    const __half* gA1 = gA0 + 64ll * lda;
    const __half* gB0 = B + (long long)(n0 + grow) * ldb + gchk * 8;
    const __half* gB1 = gB0 + 64ll * ldb;

    unsigned ssAb = (unsigned)((grow * LDSW + gchk * 8) * 2);

    unsigned base = s2u32(dsm);
    unsigned asu[3], bsu[3];
    #pragma unroll
    for (int s = 0; s < 3; s++) {
        asu[s] = base + (unsigned)(s * 2 * GEMM_TILE * 2);
        bsu[s] = asu[s] + (unsigned)(GEMM_TILE * 2);
    }

    int aBase = (wm * 32 + (lane & 15)) * LDSW + (lane >> 4) * 8;
    int bBase = (wn * 64 + (lane & 7)) * LDSW + ((lane >> 3) & 1) * 8;

    float acc[2][8][4];
    #pragma unroll
    for (int i = 0; i < 2; i++)
        #pragma unroll
        for (int j = 0; j < 8; j++) {
            acc[i][j][0] = 0.f; acc[i][j][1] = 0.f;
            acc[i][j][2] = 0.f; acc[i][j][3] = 0.f;
        }

    int nk = Kdim >> 5;

    #pragma unroll
    for (int pt = 0; pt < 2; pt++) {
        if (pt < nk) {
            int k0 = pt << 5;
            cpa16(asu[pt] + ssAb, gA0 + k0);
            cpa16(asu[pt] + ssAb + 64u * LDSW * 2u, gA1 + k0);
            cpa16(bsu[pt] + ssAb, gB0 + k0);
            cpa16(bsu[pt] + ssAb + 64u * LDSW * 2u, gB1 + k0);
        }
        cpcommit();
    }

    int stage = 0;
    for (int kt = 0; kt < nk; kt++) {
        cpwait<1>();
        __syncthreads();

        if (kt + 2 < nk) {
            int s2i = (stage + 2 >= 3) ? stage - 1 : stage + 2;
            int k0 = (kt + 2) << 5;
            cpa16(asu[s2i] + ssAb, gA0 + k0);
            cpa16(asu[s2i] + ssAb + 64u * LDSW * 2u, gA1 + k0);
            cpa16(bsu[s2i] + ssAb, gB0 + k0);
            cpa16(bsu[s2i] + ssAb + 64u * LDSW * 2u, gB1 + k0);
        }
        cpcommit();

        unsigned as_ = asu[stage];
        unsigned bs_ = bsu[stage];
        #pragma unroll
        for (int kk = 0; kk < 2; kk++) {
            unsigned af[2][4];
            unsigned bf[8][2];
            #pragma unroll
            for (int mt = 0; mt < 2; mt++)
                ldsm4(af[mt], as_ + 2u * (unsigned)(aBase + mt * 16 * LDSW + kk * 16));
            #pragma unroll
            for (int nt = 0; nt < 8; nt++)
                ldsm2(bf[nt], bs_ + 2u * (unsigned)(bBase + nt * 8 * LDSW + kk * 16));
            #pragma unroll
            for (int mt = 0; mt < 2; mt++)
                #pragma unroll
                for (int nt = 0; nt < 8; nt++)
                    mma16816(acc[mt][nt], af[mt], bf[nt]);
        }
        stage = (stage + 1 == 3) ? 0 : stage + 1;
    }

    #pragma unroll
    for (int mt = 0; mt < 2; mt++) {
        int r0 = m0 + wm * 32 + mt * 16 + (lane >> 2);
        #pragma unroll
        for (int nt = 0; nt < 8; nt++) {
            int c0 = n0 + wn * 64 + nt * 8 + (lane & 3) * 2;
            float v0 = acc[mt][nt][0] * scale;
            float v1 = acc[mt][nt][1] * scale;
            float v2 = acc[mt][nt][2] * scale;
            float v3 = acc[mt][nt][3] * scale;
            if (BIAS) {
                float bc0 = bias[c0];
                float bc1 = bias[c0 + 1];
                v0 += bc0; v1 += bc1; v2 += bc0; v3 += bc1;
            }
            store2(C, (long long)r0 * ldc + c0, v0, v1);
            store2(C, (long long)(r0 + 8) * ldc + c0, v2, v3);
        }
    }
}

__global__ __launch_bounds__(256)
void hgemm_proj3(const __half* __restrict__ x0, const __half* __restrict__ x1,
                 const __half* __restrict__ x2,
                 const __half* __restrict__ W0, const __half* __restrict__ W1,
                 const __half* __restrict__ W2,
                 __half* __restrict__ C0, __half* __restrict__ C1,
                 __half* __restrict__ C2)
{
    extern __shared__ __half dsm[];

    int z = blockIdx.z;
    const __half* A = (z == 0) ? x0 : (z == 1) ? x1 : x2;
    const __half* B = (z == 0) ? W0 : (z == 1) ? W1 : W2;
    __half* C = (z == 0) ? C0 : (z == 1) ? C1 : C2;
    float scale = (z == 0) ? SCALEF : 1.0f;

    hgemm_nt_body<__half, false>(A, B, C, Cc, Cc, Cc, Cc, scale, nullptr,
                                 blockIdx.y * 128, blockIdx.x * 128, dsm);
}

__global__ __launch_bounds__(256)
void hgemm_out(const __half* __restrict__ A, const __half* __restrict__ B,
               float* __restrict__ C, const float* __restrict__ bias)
{
    extern __shared__ __half dsm[];

    hgemm_nt_body<float, true>(A, B, C, Cc, Cc, Cc, Cc, 1.0f, bias,
                               blockIdx.y * 128, blockIdx.x * 128, dsm);
}

// ---------------------------------------------------------------------------
// Fused attention, shift-free softmax, LOW-REGISTER variant for occupancy 2.
// The 128 score columns per chunk are processed in two 64-column halves:
// sacc is [8][4] (32 regs) instead of [16][4] (64). PV accumulates per half
// (exact: PV sums over score columns). Sync loads, static 36KB smem.
// __launch_bounds__(256,2) pins regs <= 128 -> 2 CTAs/SM.
// ---------------------------------------------------------------------------
__global__ __launch_bounds__(256, 2)
void fused_attn(const __half* __restrict__ Q, const __half* __restrict__ K,
                const __half* __restrict__ V,
                const float* __restrict__ aw, float* __restrict__ log_attn,
                __half* __restrict__ O)
{
    const int LW = 72;                 // row stride in halves (64 + 8 pad)

    __shared__ alignas(16) __half Ks[128 * LW];
    __shared__ alignas(16) __half Vs[128 * LW];

    int qblk = blockIdx.x;             // 0..7
    int bh = blockIdx.y;               // 0..95
    int b = bh / Hh_;
    int h = bh - b * Hh_;

    const __half* Qp = Q + ((long long)b * Nn + qblk * 128) * Cc + h * Dd;
    const __half* Kp = K + (long long)b * Ss * Cc + h * Dd;
    const __half* Vp = V + (long long)b * Ss * Cc + h * Dd;
    const float* awp = aw + ((long long)bh * Nn + qblk * 128) * Ss;
    float* lap = log_attn + ((long long)bh * Nn + qblk * 128) * Ss;

    int tid = threadIdx.x;
    int lane = tid & 31;
    int wm = tid >> 5;

    unsigned ksu = s2u32(Ks);
    unsigned vsu = s2u32(Vs);

    int ldr = tid >> 3;                // 0..31 (row group)
    int ldc_ = (tid & 7) * 8;          // 16B chunk within row

    // ---- load Q tile into Ks, extract A fragments ----
    #pragma unroll
    for (int i = 0; i < 4; i++) {
        int row = ldr + i * 32;
        *(uint4*)&Ks[row * LW + ldc_] = *(const uint4*)(Qp + (long long)row * Cc + ldc_);
    }
    __syncthreads();

    unsigned qf[4][4];
    {
        int aBase = (wm * 16 + (lane & 15)) * LW + (lane >> 4) * 8;
        #pragma unroll
        for (int k = 0; k < 4; k++)
            ldsm4(qf[k], ksu + 2u * (unsigned)(aBase + k * 16));
    }
    __syncthreads();

    int bBaseK = (lane & 7) * LW + ((lane >> 3) & 1) * 8;

    // ================= PASS 1: LSE (shift-free) =================
    float s1[2] = { 0.f, 0.f };

    for (int c = 0; c < 8; c++) {
        #pragma unroll
        for (int i = 0; i < 4; i++) {
            int row = ldr + i * 32;
            *(uint4*)&Ks[row * LW + ldc_] =
                *(const uint4*)(Kp + (long long)(c * 128 + row) * Cc + ldc_);
        }
        __syncthreads();

        #pragma unroll
        for (int hfn = 0; hfn < 2; hfn++) {
            float sacc[8][4];
            #pragma unroll
            for (int nt = 0; nt < 8; nt++) {
                sacc[nt][0] = 0.f; sacc[nt][1] = 0.f;
                sacc[nt][2] = 0.f; sacc[nt][3] = 0.f;
            }
            #pragma unroll
            for (int kk = 0; kk < 4; kk++) {
                #pragma unroll
                for (int nt = 0; nt < 8; nt++) {
                    unsigned bf[2];
                    ldsm2(bf, ksu + 2u * (unsigned)(bBaseK + (hfn * 8 + nt) * 8 * LW + kk * 16));
                    mma16816(sacc[nt], qf[kk], bf);
                }
            }
            #pragma unroll
            for (int nt = 0; nt < 8; nt++) {
                s1[0] += __expf(sacc[nt][0]) + __expf(sacc[nt][1]);
                s1[1] += __expf(sacc[nt][2]) + __expf(sacc[nt][3]);
            }
        }
        __syncthreads();
    }

    float lse[2];
    lse[0] = __logf(quadSum(s1[0]));
    lse[1] = __logf(quadSum(s1[1]));

    // ================= PASS 2: logits + PV, per 64-column half ==============
    float s2[2] = { 0.f, 0.f };
    float oacc[8][4];
    #pragma unroll
    for (int nd = 0; nd < 8; nd++) {
        oacc[nd][0] = 0.f; oacc[nd][1] = 0.f;
        oacc[nd][2] = 0.f; oacc[nd][3] = 0.f;
    }

    int rowL0 = wm * 16 + (lane >> 2);
    int colQ = (lane & 3) * 2;

    for (int c = 0; c < 8; c++) {
        #pragma unroll
        for (int i = 0; i < 4; i++) {
            int row = ldr + i * 32;
            *(uint4*)&Ks[row * LW + ldc_] =
                *(const uint4*)(Kp + (long long)(c * 128 + row) * Cc + ldc_);
            *(uint4*)&Vs[row * LW + ldc_] =
                *(const uint4*)(Vp + (long long)(c * 128 + row) * Cc + ldc_);
        }
        __syncthreads();

        #pragma unroll
        for (int hfn = 0; hfn < 2; hfn++) {
            // QK for this 64-column half
            float sacc[8][4];
            #pragma unroll
            for (int nt = 0; nt < 8; nt++) {
                sacc[nt][0] = 0.f; sacc[nt][1] = 0.f;
                sacc[nt][2] = 0.f; sacc[nt][3] = 0.f;
            }
            #pragma unroll
            for (int kk = 0; kk < 4; kk++) {
                #pragma unroll
                for (int nt = 0; nt < 8; nt++) {
                    unsigned bf[2];
                    ldsm2(bf, ksu + 2u * (unsigned)(bBaseK + (hfn * 8 + nt) * 8 * LW + kk * 16));
                    mma16816(sacc[nt], qf[kk], bf);
                }
            }

            // logits -> log_attn, p = exp(g) -> sacc, sums
            #pragma unroll
            for (int nt = 0; nt < 8; nt++) {
                long long off0 = (long long)rowL0 * Ss + c * 128 + hfn * 64 + nt * 8 + colQ;
                long long off1 = off0 + 8ll * Ss;
                float2 wa = *(const float2*)(awp + off0);
                float2 wb = *(const float2*)(awp + off1);
                float g0 = wa.x + sacc[nt][0] - lse[0];
                float g1 = wa.y + sacc[nt][1] - lse[0];
                float g2 = wb.x + sacc[nt][2] - lse[1];
                float g3 = wb.y + sacc[nt][3] - lse[1];
                *(float2*)(lap + off0) = make_float2(g0, g1);
                *(float2*)(lap + off1) = make_float2(g2, g3);
                float p0 = __expf(g0);
                float p1 = __expf(g1);
                float p2 = __expf(g2);
                float p3 = __expf(g3);
                sacc[nt][0] = p0; sacc[nt][1] = p1;
                sacc[nt][2] = p2; sacc[nt][3] = p3;
                s2[0] += p0 + p1;
                s2[1] += p2 + p3;
            }

            // PV for this half: probs (m16 x k64) @ V rows [hfn*64, hfn*64+64)
            #pragma unroll
            for (int kk = 0; kk < 4; kk++) {
                unsigned pa[4];
                pa[0] = packh2(sacc[2 * kk][0], sacc[2 * kk][1]);
                pa[1] = packh2(sacc[2 * kk][2], sacc[2 * kk][3]);
                pa[2] = packh2(sacc[2 * kk + 1][0], sacc[2 * kk + 1][1]);
                pa[3] = packh2(sacc[2 * kk + 1][2], sacc[2 * kk + 1][3]);
                unsigned vrow = vsu + 2u * (unsigned)((hfn * 64 + kk * 16 + (lane & 15)) * LW);
                #pragma unroll
                for (int nd = 0; nd < 8; nd++) {
                    unsigned bf[2];
                    ldsm2t(bf, vrow + 2u * (unsigned)(nd * 8));
                    mma16816(oacc[nd], pa, bf);
                }
            }
        }
        __syncthreads();
    }

    // epilogue: normalize by sum(p)
    float inv0 = 1.0f / quadSum(s2[0]);
    float inv1 = 1.0f / quadSum(s2[1]);
    int gr0 = qblk * 128 + rowL0;
    #pragma unroll
    for (int nd = 0; nd < 8; nd++) {
        int col = h * Dd + nd * 8 + colQ;
        __half* p0 = O + ((long long)b * Nn + gr0) * Cc + col;
        __half* p1 = O + ((long long)b * Nn + gr0 + 8) * Cc + col;
        *(__half2*)p0 = __floats2half2_rn(oacc[nd][0] * inv0, oacc[nd][1] * inv0);
        *(__half2*)p1 = __floats2half2_rn(oacc[nd][2] * inv1, oacc[nd][3] * inv1);
    }
}

// ---------------------------------------------------------------------------
// Batched fp32 -> fp16 conversions
// ---------------------------------------------------------------------------
__global__ __launch_bounds__(256)
void f2h3(const float* __restrict__ p0, const float* __restrict__ p1,
          const float* __restrict__ p2,
          __half* __restrict__ o0, __half* __restrict__ o1,
          __half* __restrict__ o2, int n4)
{
    int i = blockIdx.x * 256 + threadIdx.x;
    if (i >= n4) return;
    int s = blockIdx.y;
    const float* in = (s == 0) ? p0 : (s == 1) ? p1 : p2;
    __half* out = (s == 0) ? o0 : (s == 1) ? o1 : o2;
    float4 v = ((const float4*)in)[i];
    __half2* o = (__half2*)out + 2 * i;
    o[0] = __floats2half2_rn(v.x, v.y);
    o[1] = __floats2half2_rn(v.z, v.w);
}

__global__ __launch_bounds__(256)
void f2h4(const float* __restrict__ p0, const float* __restrict__ p1,
          const float* __restrict__ p2, const float* __restrict__ p3,
          __half* __restrict__ o0, __half* __restrict__ o1,
          __half* __restrict__ o2, __half* __restrict__ o3, int n4)
{
    int i = blockIdx.x * 256 + threadIdx.x;
    if (i >= n4) return;
    int s = blockIdx.y;
    const float* in = (s == 0) ? p0 : (s == 1) ? p1 : (s == 2) ? p2 : p3;
    __half* out = (s == 0) ? o0 : (s == 1) ? o1 : (s == 2) ? o2 : o3;
    float4 v = ((const float4*)in)[i];
    __half2* o = (__half2*)out + 2 * i;
    o[0] = __floats2half2_rn(v.x, v.y);
    o[1] = __floats2half2_rn(v.z, v.w);
}

// ---------------------------------------------------------------------------
extern "C" void kernel_launch(void* const* d_in, const int* in_sizes, int n_in,
                              void* d_out, int out_size)
{
    const float* query = (const float*)d_in[0];
    const float* key   = (const float*)d_in[1];
    const float* value = (const float*)d_in[2];
    const float* aw    = (const float*)d_in[3];
    const float* Wq    = (const float*)d_in[4];
    const float* Wk    = (const float*)d_in[5];
    const float* Wv    = (const float*)d_in[6];
    const float* Wo    = (const float*)d_in[7];
    const float* bo    = (const float*)d_in[8];

    float* out = (float*)d_out;                               // [B,N,C]
    float* log_attn = out + (long long)Bb * Nn * Cc;          // [B,H,N,S]

    __half *q16, *k16, *v16, *Wq16, *Wk16, *Wv16, *Wo16;
    __half *Q16, *K16, *V16, *O16;
    cudaGetSymbolAddress((void**)&q16,  g_q16);
    cudaGetSymbolAddress((void**)&k16,  g_k16);
    cudaGetSymbolAddress((void**)&v16,  g_v16);
    cudaGetSymbolAddress((void**)&Wq16, g_Wq16);
    cudaGetSymbolAddress((void**)&Wk16, g_Wk16);
    cudaGetSymbolAddress((void**)&Wv16, g_Wv16);
    cudaGetSymbolAddress((void**)&Wo16, g_Wo16);
    cudaGetSymbolAddress((void**)&Q16,  g_Q16);
    cudaGetSymbolAddress((void**)&K16,  g_K16);
    cudaGetSymbolAddress((void**)&V16,  g_V16);
    cudaGetSymbolAddress((void**)&O16,  g_O16);

    // opt-in dynamic smem (idempotent)
    cudaFuncSetAttribute(hgemm_proj3,
                         cudaFuncAttributeMaxDynamicSharedMemorySize,
                         GEMM_SMEM_BYTES);
    cudaFuncSetAttribute(hgemm_out,
                         cudaFuncAttributeMaxDynamicSharedMemorySize,
                         GEMM_SMEM_BYTES);

    const int nInp4 = (Bb * Nn * Cc) / 4;      // 1572864
    const int nW4   = (Cc * Cc) / 4;           // 147456

    // Launch 1-2: conversions (fused_attn stays launch #4 for profiling)
    f2h3<<<dim3((nInp4 + 255) / 256, 3), 256>>>(query, key, value,
                                                q16, k16, v16, nInp4);
    f2h4<<<dim3((nW4 + 255) / 256, 4), 256>>>(Wq, Wk, Wv, Wo,
                                              Wq16, Wk16, Wv16, Wo16, nW4);

    dim3 blk(256);

    // Launch 3: merged Q/K/V projections (Q pre-scaled by SCALE)
    dim3 gProj3(Cc / 128, (Bb * Nn) / 128, 3);
    hgemm_proj3<<<gProj3, blk, GEMM_SMEM_BYTES>>>(q16, k16, v16,
                                                  Wq16, Wk16, Wv16,
                                                  Q16, K16, V16);

    // Launch 4: fused attention (profiled slot)
    fused_attn<<<dim3(Nn / 128, Bb * Hh_), blk>>>(Q16, K16, V16, aw, log_attn, O16);

    // Launch 5: out = O16 @ Wo16^T + bo
    dim3 gOut(Cc / 128, (Bb * Nn) / 128, 1);
    hgemm_out<<<gOut, blk, GEMM_SMEM_BYTES>>>(O16, Wo16, out, bo);
}